// round 6
// baseline (speedup 1.0000x reference)
#include <cuda_runtime.h>

#define N_EMB   512
#define EMB_D   64
#define NDP     (EMB_D / 2)        // 32 d-pairs
#define HWSZ    4096
#define NTOK    131072
#define TPB     512
#define TILE_T  128                // tokens per tile
#define NTILE   (NTOK / TILE_T)    // 1024
#define GRID_A  148

// Output packing (float32, reference tuple order)
#define OFF_RES 0ULL
#define OFF_ARG 8388608ULL
#define OFF_W   8519680ULL
#define OFF_CS  8552448ULL
#define OFF_EA  8552960ULL

// dynamic smem: wT [32][512] u64 | xT [32][128] u64 | ww [512] f32 | keys [128] u64
#define SM_WT_U64   (NDP * N_EMB)              // 16384 u64
#define SM_XT_U64   (NDP * TILE_T)             // 4096 u64
#define SMEM_BYTES  (SM_WT_U64 * 8 + SM_XT_U64 * 8 + N_EMB * 4 + TILE_T * 8)

__device__ float g_hist[N_EMB];
__device__ float g_esum[EMB_D * N_EMB];
__device__ float g_ww[N_EMB];
__device__ unsigned long long g_wt2[SM_WT_U64];   // [dpair][j] packed f32x2
__device__ unsigned int g_work;
__device__ unsigned int g_done;

__device__ __forceinline__ unsigned long long ffma2(unsigned long long a,
                                                    unsigned long long b,
                                                    unsigned long long c) {
    unsigned long long d;
    asm("fma.rn.f32x2 %0, %1, %2, %3;" : "=l"(d) : "l"(a), "l"(b), "l"(c));
    return d;
}

__device__ __forceinline__ unsigned long long pack2(float lo, float hi) {
    unsigned long long r;
    asm("mov.b64 %0, {%1, %2};" : "=l"(r)
        : "r"(__float_as_uint(lo)), "r"(__float_as_uint(hi)));
    return r;
}

__device__ __forceinline__ void unpack2(unsigned long long v, float& lo, float& hi) {
    unsigned int a, b;
    asm("mov.b64 {%0, %1}, %2;" : "=r"(a), "=r"(b) : "l"(v));
    lo = __uint_as_float(a);
    hi = __uint_as_float(b);
}

// ---------------------------------------------------------------------------
// prep: zero scratch, build packed transposed codebook + ||w||^2, reset ctrs
// ---------------------------------------------------------------------------
__global__ void prep_kernel(const float* __restrict__ w) {
    int idx = blockIdx.x * blockDim.x + threadIdx.x;   // 0..32767
    if (idx == 0) { g_work = 0u; g_done = 0u; }
    if (idx < EMB_D * N_EMB) g_esum[idx] = 0.0f;
    if (idx < SM_WT_U64) {
        int dd = idx >> 9;           // d-pair
        int j  = idx & (N_EMB - 1);
        g_wt2[idx] = pack2(w[(2 * dd) * N_EMB + j], w[(2 * dd + 1) * N_EMB + j]);
    }
    if (idx < N_EMB) {
        g_hist[idx] = 0.0f;
        float s = 0.0f;
        #pragma unroll
        for (int d = 0; d < EMB_D; d++) {
            float v = w[d * N_EMB + idx];
            s = __fadd_rn(s, __fmul_rn(v, v));
        }
        g_ww[idx] = s;
    }
}

// ---------------------------------------------------------------------------
// assign: register-tiled GEMM-style scan.
// 512 thr/CTA = (tx 0..31) x (ty 0..15). Tile = 128 tokens.
// Each thread: 8 tokens x 4 codewords accumulators; 4 passes cover 512 j.
// Cross-thread argmin via packed-key smem atomicMin.
// ---------------------------------------------------------------------------
extern __shared__ unsigned long long smem_u64[];

__global__ void __launch_bounds__(TPB, 1)
assign_kernel(const float* __restrict__ x,
              const float* __restrict__ cs_in,
              const float* __restrict__ ea_in,
              float* __restrict__ out) {
    unsigned long long* wTs  = smem_u64;                    // [32][512]
    unsigned long long* xTs  = smem_u64 + SM_WT_U64;        // [32][128]
    float*              ww_s = (float*)(xTs + SM_XT_U64);   // [512]
    unsigned long long* keys = (unsigned long long*)(ww_s + N_EMB); // [128]

    __shared__ int s_chunk;
    __shared__ unsigned int s_rank;

    int tid = threadIdx.x;
    int tx  = tid & 31;
    int ty  = tid >> 5;

    // Stage packed codebook (coalesced ulonglong2) + ww
    {
        const ulonglong2* src = (const ulonglong2*)g_wt2;
        ulonglong2* dst = (ulonglong2*)wTs;
        #pragma unroll
        for (int i = 0; i < (SM_WT_U64 / 2) / TPB; i++)   // 16 iters
            dst[i * TPB + tid] = src[i * TPB + tid];
        ww_s[tid] = g_ww[tid];
    }

    for (;;) {
        __syncthreads();
        if (tid == 0) s_chunk = (int)atomicAdd(&g_work, 1u);
        __syncthreads();
        int tile = s_chunk;
        if (tile >= NTILE) break;

        int t0g = tile * TILE_T;            // tile never crosses a batch
        int b   = t0g >> 12;
        int hw0 = t0g & (HWSZ - 1);
        const float* xb = x + (size_t)b * EMB_D * HWSZ + hw0;

        // Load x tile transposed into smem; init keys
        if (tid < TILE_T) keys[tid] = ~0ULL;
        #pragma unroll
        for (int r = 0; r < (SM_XT_U64 / TPB); r++) {     // 8 iters
            int idx = tid + TPB * r;
            int dd  = idx >> 7;
            int t   = idx & (TILE_T - 1);
            xTs[idx] = pack2(xb[(2 * dd) * HWSZ + t], xb[(2 * dd + 1) * HWSZ + t]);
        }
        __syncthreads();

        int tloc = ty * 8;     // this thread's 8 tokens within tile

        #pragma unroll 1
        for (int pass = 0; pass < 4; pass++) {
            int jb = pass * 128 + tx;        // codewords jb + 32k, k=0..3
            const unsigned long long* wbase = wTs + jb;
            const unsigned long long* xbase = xTs + tloc;

            unsigned long long acc[8][4];
            #pragma unroll
            for (int t = 0; t < 8; t++)
                #pragma unroll
                for (int k = 0; k < 4; k++) acc[t][k] = 0ULL;

            #pragma unroll
            for (int dd = 0; dd < NDP; dd++) {
                unsigned long long wv0 = wbase[dd * N_EMB + 0];
                unsigned long long wv1 = wbase[dd * N_EMB + 32];
                unsigned long long wv2 = wbase[dd * N_EMB + 64];
                unsigned long long wv3 = wbase[dd * N_EMB + 96];
                #pragma unroll
                for (int t = 0; t < 8; t++) {
                    unsigned long long xv = xbase[dd * TILE_T + t];
                    acc[t][0] = ffma2(xv, wv0, acc[t][0]);
                    acc[t][1] = ffma2(xv, wv1, acc[t][1]);
                    acc[t][2] = ffma2(xv, wv2, acc[t][2]);
                    acc[t][3] = ffma2(xv, wv3, acc[t][3]);
                }
            }

            // local best over this thread's 4 codewords (ascending j), then
            // global combine via packed-key atomicMin (min dist, tie -> min j)
            float w0 = ww_s[jb + 0], w1 = ww_s[jb + 32];
            float w2 = ww_s[jb + 64], w3 = ww_s[jb + 96];
            #pragma unroll
            for (int t = 0; t < 8; t++) {
                float lo, hi;
                unpack2(acc[t][0], lo, hi);
                float d0 = __fmaf_rn(-2.0f, __fadd_rn(lo, hi), w0);
                unpack2(acc[t][1], lo, hi);
                float d1 = __fmaf_rn(-2.0f, __fadd_rn(lo, hi), w1);
                unpack2(acc[t][2], lo, hi);
                float d2 = __fmaf_rn(-2.0f, __fadd_rn(lo, hi), w2);
                unpack2(acc[t][3], lo, hi);
                float d3 = __fmaf_rn(-2.0f, __fadd_rn(lo, hi), w3);

                float best = d0; int bj = jb;
                if (d1 < best) { best = d1; bj = jb + 32; }
                if (d2 < best) { best = d2; bj = jb + 64; }
                if (d3 < best) { best = d3; bj = jb + 96; }

                unsigned int s = __float_as_uint(best);
                s = (s & 0x80000000u) ? ~s : (s | 0x80000000u);
                unsigned long long key =
                    ((unsigned long long)s << 32) | (unsigned int)bj;
                atomicMin(&keys[tloc + t], key);
            }
        }
        __syncthreads();

        // ----- epilogue: 4 d-groups x 128 tokens across 512 threads -----
        int tk = tid & (TILE_T - 1);
        int dg = tid >> 7;                 // 0..3, 8 d-pairs each
        int bi = (int)(keys[tk] & 0xFFFFFFFFULL);

        if (dg == 0) {
            out[OFF_ARG + (size_t)(t0g + tk)] = (float)bi;
            atomicAdd(&g_hist[bi], 1.0f);
        }

        float* ro = out + (size_t)b * EMB_D * HWSZ + hw0 + tk;
        #pragma unroll
        for (int q = 0; q < 8; q++) {
            int dd = dg * 8 + q;
            float lo, hi;
            unpack2(wTs[dd * N_EMB + bi], lo, hi);
            ro[(2 * dd)     * HWSZ] = lo;
            ro[(2 * dd + 1) * HWSZ] = hi;
            float xlo, xhi;
            unpack2(xTs[dd * TILE_T + tk], xlo, xhi);
            atomicAdd(&g_esum[(2 * dd)     * N_EMB + bi], xlo);
            atomicAdd(&g_esum[(2 * dd + 1) * N_EMB + bi], xhi);
        }
    }

    // ------- merged finalize: last CTA does the EMA update -------
    __threadfence();
    __syncthreads();
    if (tid == 0) s_rank = atomicAdd(&g_done, 1u);
    __syncthreads();
    if (s_rank == GRID_A - 1) {
        float* red = (float*)smem_u64;
        int j = tid;                       // TPB == N_EMB == 512

        const float DEC  = 0.99f;
        const float OMD  = (float)(1.0 - 0.99);
        const float EPSF = (float)1e-5;
        const float NEPS = (float)(N_EMB * 1e-5);

        float nidx = g_hist[j];
        if (nidx == 0.0f) nidx = 1.0f;
        float ncs = __fadd_rn(__fmul_rn(DEC, cs_in[j]), __fmul_rn(OMD, nidx));

        __syncthreads();
        red[j] = ncs;
        __syncthreads();
        #pragma unroll
        for (int s = N_EMB / 2; s > 0; s >>= 1) {
            if (j < s) red[j] += red[j + s];
            __syncthreads();
        }
        float n = red[0];

        float csn = __fmul_rn(__fdiv_rn(__fadd_rn(ncs, EPSF),
                                        __fadd_rn(n, NEPS)), n);

        out[OFF_CS + j] = ncs;

        for (int d = 0; d < EMB_D; d++) {
            int idx = d * N_EMB + j;
            float e = __fadd_rn(__fmul_rn(DEC, ea_in[idx]),
                                __fmul_rn(OMD, g_esum[idx]));
            out[OFF_EA + idx] = e;
            out[OFF_W  + idx] = __fdiv_rn(e, csn);
        }
    }
}

// ---------------------------------------------------------------------------
extern "C" void kernel_launch(void* const* d_in, const int* in_sizes, int n_in,
                              void* d_out, int out_size) {
    const float* x  = (const float*)d_in[0];
    const float* w  = (const float*)d_in[1];
    const float* cs = (const float*)d_in[2];
    const float* ea = (const float*)d_in[3];
    float* out = (float*)d_out;

    cudaFuncSetAttribute(assign_kernel,
                         cudaFuncAttributeMaxDynamicSharedMemorySize, SMEM_BYTES);

    prep_kernel<<<128, 256>>>(w);
    assign_kernel<<<GRID_A, TPB, SMEM_BYTES>>>(x, cs, ea, out);
}

// round 7
// speedup vs baseline: 2.3076x; 2.3076x over previous
#include <cuda_runtime.h>

#define N_EMB   512
#define EMB_D   64
#define NDP     (EMB_D / 2)        // 32 d-pairs
#define HWSZ    4096
#define NTOK    131072
#define TPB     512
#define TILE_T  64                 // tokens per tile
#define NTILE   (NTOK / TILE_T)    // 2048
#define GRID_A  148

// Output packing (float32, reference tuple order)
#define OFF_RES 0ULL
#define OFF_ARG 8388608ULL
#define OFF_W   8519680ULL
#define OFF_CS  8552448ULL
#define OFF_EA  8552960ULL

// dynamic smem: wT [32][512] u64 | xT [32][64] u64 | ww [512] f32 | keys [64] u64
#define SM_WT_U64   (NDP * N_EMB)              // 16384 u64 = 128 KB
#define SM_XT_U64   (NDP * TILE_T)             // 2048 u64  = 16 KB
#define SMEM_BYTES  (SM_WT_U64 * 8 + SM_XT_U64 * 8 + N_EMB * 4 + TILE_T * 8)

__device__ float g_hist[N_EMB];
__device__ float g_esum[EMB_D * N_EMB];
__device__ float g_ww[N_EMB];
__device__ unsigned long long g_wt2[SM_WT_U64];   // [dpair][j] packed f32x2
__device__ unsigned int g_work;
__device__ unsigned int g_done;

__device__ __forceinline__ unsigned long long ffma2(unsigned long long a,
                                                    unsigned long long b,
                                                    unsigned long long c) {
    unsigned long long d;
    asm("fma.rn.f32x2 %0, %1, %2, %3;" : "=l"(d) : "l"(a), "l"(b), "l"(c));
    return d;
}

__device__ __forceinline__ unsigned long long pack2(float lo, float hi) {
    unsigned long long r;
    asm("mov.b64 %0, {%1, %2};" : "=l"(r)
        : "r"(__float_as_uint(lo)), "r"(__float_as_uint(hi)));
    return r;
}

__device__ __forceinline__ void unpack2(unsigned long long v, float& lo, float& hi) {
    unsigned int a, b;
    asm("mov.b64 {%0, %1}, %2;" : "=r"(a), "=r"(b) : "l"(v));
    lo = __uint_as_float(a);
    hi = __uint_as_float(b);
}

// ---------------------------------------------------------------------------
// prep: zero scratch, packed transposed codebook + ||w||^2, reset counters
// ---------------------------------------------------------------------------
__global__ void prep_kernel(const float* __restrict__ w) {
    int idx = blockIdx.x * blockDim.x + threadIdx.x;   // 0..32767
    if (idx == 0) { g_work = 0u; g_done = 0u; }
    if (idx < EMB_D * N_EMB) g_esum[idx] = 0.0f;
    if (idx < SM_WT_U64) {
        int dd = idx >> 9;
        int j  = idx & (N_EMB - 1);
        g_wt2[idx] = pack2(w[(2 * dd) * N_EMB + j], w[(2 * dd + 1) * N_EMB + j]);
    }
    if (idx < N_EMB) {
        g_hist[idx] = 0.0f;
        float s = 0.0f;
        #pragma unroll
        for (int d = 0; d < EMB_D; d++) {
            float v = w[d * N_EMB + idx];
            s = __fadd_rn(s, __fmul_rn(v, v));
        }
        g_ww[idx] = s;
    }
}

// ---------------------------------------------------------------------------
// assign: register-tiled scan. 512 thr = (tx 0..31) x (ty 0..15).
// Tile = 64 tokens; each thread owns 4 tokens x 4 codewords; 4 passes
// cover all 512 j. Per-token best kept in registers across passes,
// combined with a u64 shfl butterfly min (no atomics).
// ---------------------------------------------------------------------------
extern __shared__ unsigned long long smem_u64[];

__global__ void __launch_bounds__(TPB, 1)
assign_kernel(const float* __restrict__ x,
              const float* __restrict__ cs_in,
              const float* __restrict__ ea_in,
              float* __restrict__ out) {
    unsigned long long* wTs  = smem_u64;                    // [32][512]
    unsigned long long* xTs  = smem_u64 + SM_WT_U64;        // [32][64]
    float*              ww_s = (float*)(xTs + SM_XT_U64);   // [512]
    unsigned long long* keys = (unsigned long long*)(ww_s + N_EMB); // [64]

    __shared__ int s_chunk;
    __shared__ unsigned int s_rank;

    int tid = threadIdx.x;
    int tx  = tid & 31;
    int ty  = tid >> 5;
    int tloc = ty * 4;          // this warp's 4 tokens

    // Stage packed codebook (coalesced ulonglong2) + ww
    {
        const ulonglong2* src = (const ulonglong2*)g_wt2;
        ulonglong2* dst = (ulonglong2*)wTs;
        #pragma unroll
        for (int i = 0; i < (SM_WT_U64 / 2) / TPB; i++)   // 16 iters
            dst[i * TPB + tid] = src[i * TPB + tid];
        ww_s[tid] = g_ww[tid];
    }

    for (;;) {
        __syncthreads();
        if (tid == 0) s_chunk = (int)atomicAdd(&g_work, 1u);
        __syncthreads();
        int tile = s_chunk;
        if (tile >= NTILE) break;

        int t0g = tile * TILE_T;            // tile never crosses a batch
        int b   = t0g >> 12;
        int hw0 = t0g & (HWSZ - 1);
        const float* xb = x + (size_t)b * EMB_D * HWSZ + hw0;

        // Load x tile transposed into smem: xT[dd][t]
        #pragma unroll
        for (int r = 0; r < (SM_XT_U64 / TPB); r++) {     // 4 iters
            int idx = tid + TPB * r;
            int dd  = idx >> 6;
            int t   = idx & (TILE_T - 1);
            xTs[idx] = pack2(xb[(2 * dd) * HWSZ + t], xb[(2 * dd + 1) * HWSZ + t]);
        }
        __syncthreads();

        unsigned long long bk0 = ~0ULL, bk1 = ~0ULL, bk2 = ~0ULL, bk3 = ~0ULL;

        #pragma unroll 1
        for (int pass = 0; pass < 4; pass++) {
            int jb = pass * 128 + tx;        // codewords jb + 32k, k=0..3
            const unsigned long long* wbase = wTs + jb;
            const unsigned long long* xbase = xTs + tloc;

            unsigned long long acc[4][4];
            #pragma unroll
            for (int t = 0; t < 4; t++)
                #pragma unroll
                for (int k = 0; k < 4; k++) acc[t][k] = 0ULL;

            #pragma unroll
            for (int dd = 0; dd < NDP; dd++) {
                unsigned long long wv0 = wbase[dd * N_EMB + 0];
                unsigned long long wv1 = wbase[dd * N_EMB + 32];
                unsigned long long wv2 = wbase[dd * N_EMB + 64];
                unsigned long long wv3 = wbase[dd * N_EMB + 96];
                #pragma unroll
                for (int t = 0; t < 4; t++) {
                    unsigned long long xv = xbase[dd * TILE_T + t];
                    acc[t][0] = ffma2(xv, wv0, acc[t][0]);
                    acc[t][1] = ffma2(xv, wv1, acc[t][1]);
                    acc[t][2] = ffma2(xv, wv2, acc[t][2]);
                    acc[t][3] = ffma2(xv, wv3, acc[t][3]);
                }
            }

            float w0 = ww_s[jb + 0], w1 = ww_s[jb + 32];
            float w2 = ww_s[jb + 64], w3 = ww_s[jb + 96];
            #pragma unroll
            for (int t = 0; t < 4; t++) {
                float lo, hi;
                unpack2(acc[t][0], lo, hi);
                float d0 = __fmaf_rn(-2.0f, __fadd_rn(lo, hi), w0);
                unpack2(acc[t][1], lo, hi);
                float d1 = __fmaf_rn(-2.0f, __fadd_rn(lo, hi), w1);
                unpack2(acc[t][2], lo, hi);
                float d2 = __fmaf_rn(-2.0f, __fadd_rn(lo, hi), w2);
                unpack2(acc[t][3], lo, hi);
                float d3 = __fmaf_rn(-2.0f, __fadd_rn(lo, hi), w3);

                // sortable encode: min over (dist, j) == min dist, tie -> min j
                unsigned int s0 = __float_as_uint(d0);
                s0 = (s0 & 0x80000000u) ? ~s0 : (s0 | 0x80000000u);
                unsigned int s1 = __float_as_uint(d1);
                s1 = (s1 & 0x80000000u) ? ~s1 : (s1 | 0x80000000u);
                unsigned int s2 = __float_as_uint(d2);
                s2 = (s2 & 0x80000000u) ? ~s2 : (s2 | 0x80000000u);
                unsigned int s3 = __float_as_uint(d3);
                s3 = (s3 & 0x80000000u) ? ~s3 : (s3 | 0x80000000u);

                unsigned long long k0 = ((unsigned long long)s0 << 32) | (unsigned int)(jb);
                unsigned long long k1 = ((unsigned long long)s1 << 32) | (unsigned int)(jb + 32);
                unsigned long long k2 = ((unsigned long long)s2 << 32) | (unsigned int)(jb + 64);
                unsigned long long k3 = ((unsigned long long)s3 << 32) | (unsigned int)(jb + 96);

                unsigned long long km = k0;
                if (k1 < km) km = k1;
                if (k2 < km) km = k2;
                if (k3 < km) km = k3;

                if (t == 0) { if (km < bk0) bk0 = km; }
                else if (t == 1) { if (km < bk1) bk1 = km; }
                else if (t == 2) { if (km < bk2) bk2 = km; }
                else             { if (km < bk3) bk3 = km; }
            }
        }

        // warp-level u64 min reduce (all 512 j per token live in this warp)
        #pragma unroll
        for (int off = 16; off > 0; off >>= 1) {
            unsigned long long o0 = __shfl_xor_sync(0xFFFFFFFFu, bk0, off);
            unsigned long long o1 = __shfl_xor_sync(0xFFFFFFFFu, bk1, off);
            unsigned long long o2 = __shfl_xor_sync(0xFFFFFFFFu, bk2, off);
            unsigned long long o3 = __shfl_xor_sync(0xFFFFFFFFu, bk3, off);
            if (o0 < bk0) bk0 = o0;
            if (o1 < bk1) bk1 = o1;
            if (o2 < bk2) bk2 = o2;
            if (o3 < bk3) bk3 = o3;
        }
        if (tx == 0) {
            keys[tloc + 0] = bk0;
            keys[tloc + 1] = bk1;
            keys[tloc + 2] = bk2;
            keys[tloc + 3] = bk3;
        }
        __syncthreads();

        // ----- epilogue: 8 d-groups x 64 tokens across 512 threads -----
        int tk = tid & (TILE_T - 1);
        int dg = tid >> 6;                 // 0..7, 4 d-pairs each
        int bi = (int)(keys[tk] & 0xFFFFFFFFULL);

        if (dg == 0) {
            out[OFF_ARG + (size_t)(t0g + tk)] = (float)bi;
            atomicAdd(&g_hist[bi], 1.0f);
        }

        float* ro = out + (size_t)b * EMB_D * HWSZ + hw0 + tk;
        #pragma unroll
        for (int q = 0; q < 4; q++) {
            int dd = dg * 4 + q;
            float lo, hi;
            unpack2(wTs[dd * N_EMB + bi], lo, hi);
            ro[(2 * dd)     * HWSZ] = lo;
            ro[(2 * dd + 1) * HWSZ] = hi;
            float xlo, xhi;
            unpack2(xTs[dd * TILE_T + tk], xlo, xhi);
            atomicAdd(&g_esum[(2 * dd)     * N_EMB + bi], xlo);
            atomicAdd(&g_esum[(2 * dd + 1) * N_EMB + bi], xhi);
        }
    }

    // ------- merged finalize: last CTA does the EMA update -------
    __threadfence();
    __syncthreads();
    if (tid == 0) s_rank = atomicAdd(&g_done, 1u);
    __syncthreads();
    if (s_rank == GRID_A - 1) {
        float* red = (float*)smem_u64;
        int j = tid;                       // TPB == N_EMB == 512

        const float DEC  = 0.99f;
        const float OMD  = (float)(1.0 - 0.99);
        const float EPSF = (float)1e-5;
        const float NEPS = (float)(N_EMB * 1e-5);

        float nidx = g_hist[j];
        if (nidx == 0.0f) nidx = 1.0f;
        float ncs = __fadd_rn(__fmul_rn(DEC, cs_in[j]), __fmul_rn(OMD, nidx));

        __syncthreads();
        red[j] = ncs;
        __syncthreads();
        #pragma unroll
        for (int s = N_EMB / 2; s > 0; s >>= 1) {
            if (j < s) red[j] += red[j + s];
            __syncthreads();
        }
        float n = red[0];

        float csn = __fmul_rn(__fdiv_rn(__fadd_rn(ncs, EPSF),
                                        __fadd_rn(n, NEPS)), n);

        out[OFF_CS + j] = ncs;

        for (int d = 0; d < EMB_D; d++) {
            int idx = d * N_EMB + j;
            float e = __fadd_rn(__fmul_rn(DEC, ea_in[idx]),
                                __fmul_rn(OMD, g_esum[idx]));
            out[OFF_EA + idx] = e;
            out[OFF_W  + idx] = __fdiv_rn(e, csn);
        }
    }
}

// ---------------------------------------------------------------------------
extern "C" void kernel_launch(void* const* d_in, const int* in_sizes, int n_in,
                              void* d_out, int out_size) {
    const float* x  = (const float*)d_in[0];
    const float* w  = (const float*)d_in[1];
    const float* cs = (const float*)d_in[2];
    const float* ea = (const float*)d_in[3];
    float* out = (float*)d_out;

    cudaFuncSetAttribute(assign_kernel,
                         cudaFuncAttributeMaxDynamicSharedMemorySize, SMEM_BYTES);

    prep_kernel<<<128, 256>>>(w);
    assign_kernel<<<GRID_A, TPB, SMEM_BYTES>>>(x, cs, ea, out);
}

// round 8
// speedup vs baseline: 9.1798x; 3.9780x over previous
#include <cuda_runtime.h>

#define N_EMB   512
#define EMB_D   64
#define HWSZ    4096
#define NTOK    131072
#define TPB     256
#define TOKS_PER_CHUNK (TPB * 2)          // T=2 tokens per thread
#define NCHUNK  (NTOK / TOKS_PER_CHUNK)   // 256
#define GRID_A  148
#define NREP    8

// Output packing (float32, reference tuple order)
#define OFF_RES 0ULL
#define OFF_ARG 8388608ULL
#define OFF_W   8519680ULL
#define OFF_CS  8552448ULL
#define OFF_EA  8552960ULL

#define SMEM_BYTES ((N_EMB * EMB_D + N_EMB) * 4)   // 133120 B

__device__ float g_histR[NREP][N_EMB];
__device__ float g_esumR[NREP][EMB_D * N_EMB];
__device__ float g_ww[N_EMB];
__device__ float g_wt[N_EMB * EMB_D];   // weight transposed: [j][d]
__device__ unsigned int g_work;
__device__ unsigned int g_done;

__device__ __forceinline__ unsigned long long ffma2(unsigned long long a,
                                                    unsigned long long b,
                                                    unsigned long long c) {
    unsigned long long d;
    asm("fma.rn.f32x2 %0, %1, %2, %3;" : "=l"(d) : "l"(a), "l"(b), "l"(c));
    return d;
}

__device__ __forceinline__ unsigned long long fadd2(unsigned long long a,
                                                    unsigned long long b) {
    unsigned long long d;
    asm("add.rn.f32x2 %0, %1, %2;" : "=l"(d) : "l"(a), "l"(b));
    return d;
}

__device__ __forceinline__ unsigned long long pack2(float lo, float hi) {
    unsigned long long r;
    asm("mov.b64 %0, {%1, %2};" : "=l"(r)
        : "r"(__float_as_uint(lo)), "r"(__float_as_uint(hi)));
    return r;
}

__device__ __forceinline__ void unpack2(unsigned long long v, float& lo, float& hi) {
    unsigned int a, b;
    asm("mov.b64 {%0, %1}, %2;" : "=r"(a), "=r"(b) : "l"(v));
    lo = __uint_as_float(a);
    hi = __uint_as_float(b);
}

// ---------------------------------------------------------------------------
// prep: zero replicated scratch, transpose weight, ||w||^2, reset counters
// ---------------------------------------------------------------------------
__global__ void prep_kernel(const float* __restrict__ w) {
    int idx = blockIdx.x * blockDim.x + threadIdx.x;   // 0..32767
    if (idx == 0) { g_work = 0u; g_done = 0u; }
    if (idx < EMB_D * N_EMB) {
        #pragma unroll
        for (int r = 0; r < NREP; r++) g_esumR[r][idx] = 0.0f;
        int j = idx >> 6;
        int d = idx & 63;
        g_wt[idx] = w[d * N_EMB + j];
    }
    if (idx < N_EMB) {
        #pragma unroll
        for (int r = 0; r < NREP; r++) g_histR[r][idx] = 0.0f;
        float s = 0.0f;
        #pragma unroll
        for (int d = 0; d < EMB_D; d++) {
            float v = w[d * N_EMB + idx];
            s = __fadd_rn(s, __fmul_rn(v, v));
        }
        g_ww[idx] = s;
    }
}

// ---------------------------------------------------------------------------
// assign: R4 compute core (persistent, T=2 tokens/thread) + de-serialized
// EMA atomics (warp-aggregated hist, 8x replicated accumulators).
// ---------------------------------------------------------------------------
extern __shared__ float smem_dyn[];

__global__ void __launch_bounds__(TPB, 1)
assign_kernel(const float* __restrict__ x,
              const float* __restrict__ cs_in,
              const float* __restrict__ ea_in,
              float* __restrict__ out) {
    float* w_s  = smem_dyn;                     // [512][64] j-major
    float* ww_s = smem_dyn + N_EMB * EMB_D;     // [512]
    __shared__ int s_chunk;
    __shared__ unsigned int s_rank;

    int tid  = threadIdx.x;
    int lane = tid & 31;
    int rep  = blockIdx.x & (NREP - 1);
    float* histR = g_histR[rep];
    float* esumR = g_esumR[rep];

    // Stage transposed weight once per CTA: coalesced, conflict-free
    {
        const float4* src = (const float4*)g_wt;
        float4* dst = (float4*)w_s;
        #pragma unroll
        for (int i = 0; i < (N_EMB * EMB_D / 4) / TPB; i++)
            dst[i * TPB + tid] = src[i * TPB + tid];
        ww_s[tid]       = g_ww[tid];
        ww_s[tid + 256] = g_ww[tid + 256];
    }

    for (;;) {
        __syncthreads();
        if (tid == 0) s_chunk = (int)atomicAdd(&g_work, 1u);
        __syncthreads();
        int c = s_chunk;
        if (c >= NCHUNK) break;

        // chunk = 512 consecutive tokens, never crosses a batch
        int t0 = c * TOKS_PER_CHUNK + tid;     // token A; token B = t0+256
        int b0 = t0 >> 12;
        int hw0 = t0 & (HWSZ - 1);
        const float* xa_p = x + (size_t)b0 * EMB_D * HWSZ + hw0;

        unsigned long long xpa[EMB_D / 2];
        unsigned long long xpb[EMB_D / 2];
        #pragma unroll
        for (int i = 0; i < EMB_D / 2; i++) {
            xpa[i] = pack2(xa_p[(2 * i) * HWSZ],       xa_p[(2 * i + 1) * HWSZ]);
            xpb[i] = pack2(xa_p[(2 * i) * HWSZ + 256], xa_p[(2 * i + 1) * HWSZ + 256]);
        }

        float bestA = 3.4e38f, bestB = 3.4e38f;
        int   biA = 0, biB = 0;

        #pragma unroll 1
        for (int j0 = 0; j0 < N_EMB; j0 += 2) {
            const ulonglong2* r0 = (const ulonglong2*)(w_s + (j0 + 0) * EMB_D);
            const ulonglong2* r1 = (const ulonglong2*)(w_s + (j0 + 1) * EMB_D);

            unsigned long long a0Ae = 0ULL, a0Ao = 0ULL, a0Be = 0ULL, a0Bo = 0ULL;
            unsigned long long a1Ae = 0ULL, a1Ao = 0ULL, a1Be = 0ULL, a1Bo = 0ULL;

            #pragma unroll
            for (int q = 0; q < EMB_D / 4; q++) {
                ulonglong2 v0 = r0[q];     // broadcast LDS.128
                ulonglong2 v1 = r1[q];
                unsigned long long xaE = xpa[2 * q], xaO = xpa[2 * q + 1];
                unsigned long long xbE = xpb[2 * q], xbO = xpb[2 * q + 1];
                a0Ae = ffma2(xaE, v0.x, a0Ae);  a0Ao = ffma2(xaO, v0.y, a0Ao);
                a0Be = ffma2(xbE, v0.x, a0Be);  a0Bo = ffma2(xbO, v0.y, a0Bo);
                a1Ae = ffma2(xaE, v1.x, a1Ae);  a1Ao = ffma2(xaO, v1.y, a1Ao);
                a1Be = ffma2(xbE, v1.x, a1Be);  a1Bo = ffma2(xbO, v1.y, a1Bo);
            }

            float lo, hi;
            float w0 = ww_s[j0], w1 = ww_s[j0 + 1];
            unpack2(fadd2(a0Ae, a0Ao), lo, hi);
            float d0A = __fmaf_rn(-2.0f, __fadd_rn(lo, hi), w0);
            unpack2(fadd2(a1Ae, a1Ao), lo, hi);
            float d1A = __fmaf_rn(-2.0f, __fadd_rn(lo, hi), w1);
            unpack2(fadd2(a0Be, a0Bo), lo, hi);
            float d0B = __fmaf_rn(-2.0f, __fadd_rn(lo, hi), w0);
            unpack2(fadd2(a1Be, a1Bo), lo, hi);
            float d1B = __fmaf_rn(-2.0f, __fadd_rn(lo, hi), w1);

            if (d0A < bestA) { bestA = d0A; biA = j0;     }
            if (d1A < bestA) { bestA = d1A; biA = j0 + 1; }
            if (d0B < bestB) { bestB = d0B; biB = j0;     }
            if (d1B < bestB) { bestB = d1B; biB = j0 + 1; }
        }

        out[OFF_ARG + (size_t)t0]       = (float)biA;
        out[OFF_ARG + (size_t)t0 + 256] = (float)biB;

        // quantized result from smem codebook
        {
            float* ro = out + (size_t)b0 * EMB_D * HWSZ + hw0;
            const float4* wrowA = (const float4*)(w_s + biA * EMB_D);
            const float4* wrowB = (const float4*)(w_s + biB * EMB_D);
            #pragma unroll
            for (int i = 0; i < EMB_D / 4; i++) {
                float4 va = wrowA[i];
                float4 vb = wrowB[i];
                ro[(4 * i + 0) * HWSZ]       = va.x;
                ro[(4 * i + 1) * HWSZ]       = va.y;
                ro[(4 * i + 2) * HWSZ]       = va.z;
                ro[(4 * i + 3) * HWSZ]       = va.w;
                ro[(4 * i + 0) * HWSZ + 256] = vb.x;
                ro[(4 * i + 1) * HWSZ + 256] = vb.y;
                ro[(4 * i + 2) * HWSZ + 256] = vb.z;
                ro[(4 * i + 3) * HWSZ + 256] = vb.w;
            }
        }

        // hist: warp-aggregated (one add per distinct index per warp)
        {
            unsigned int mA = __match_any_sync(0xFFFFFFFFu, biA);
            if ((int)(__ffs(mA) - 1) == lane)
                atomicAdd(&histR[biA], (float)__popc(mA));
            unsigned int mB = __match_any_sync(0xFFFFFFFFu, biB);
            if ((int)(__ffs(mB) - 1) == lane)
                atomicAdd(&histR[biB], (float)__popc(mB));
        }

        // esum: replicated accumulators (hot-address chains / NREP)
        #pragma unroll
        for (int i = 0; i < EMB_D / 2; i++) {
            float lo, hi;
            unpack2(xpa[i], lo, hi);
            atomicAdd(&esumR[(2 * i)     * N_EMB + biA], lo);
            atomicAdd(&esumR[(2 * i + 1) * N_EMB + biA], hi);
            unpack2(xpb[i], lo, hi);
            atomicAdd(&esumR[(2 * i)     * N_EMB + biB], lo);
            atomicAdd(&esumR[(2 * i + 1) * N_EMB + biB], hi);
        }
    }

    // ------- merged finalize: last CTA does the EMA update -------
    __threadfence();
    __syncthreads();
    if (tid == 0) s_rank = atomicAdd(&g_done, 1u);
    __syncthreads();
    if (s_rank == GRID_A - 1) {
        float* red = smem_dyn;

        const float DEC  = 0.99f;
        const float OMD  = (float)(1.0 - 0.99);
        const float EPSF = (float)1e-5;
        const float NEPS = (float)(N_EMB * 1e-5);

        float ncs0, ncs1;
        {
            float n0 = 0.0f, n1 = 0.0f;
            #pragma unroll
            for (int r = 0; r < NREP; r++) {
                n0 += g_histR[r][tid];
                n1 += g_histR[r][tid + 256];
            }
            if (n0 == 0.0f) n0 = 1.0f;
            if (n1 == 0.0f) n1 = 1.0f;
            ncs0 = __fadd_rn(__fmul_rn(DEC, cs_in[tid]), __fmul_rn(OMD, n0));
            ncs1 = __fadd_rn(__fmul_rn(DEC, cs_in[tid + 256]), __fmul_rn(OMD, n1));
        }

        __syncthreads();
        red[tid] = ncs0 + ncs1;
        __syncthreads();
        #pragma unroll
        for (int s = 128; s > 0; s >>= 1) {
            if (tid < s) red[tid] += red[tid + s];
            __syncthreads();
        }
        float n = red[0];

        float csn0 = __fmul_rn(__fdiv_rn(__fadd_rn(ncs0, EPSF),
                                         __fadd_rn(n, NEPS)), n);
        float csn1 = __fmul_rn(__fdiv_rn(__fadd_rn(ncs1, EPSF),
                                         __fadd_rn(n, NEPS)), n);

        out[OFF_CS + tid]       = ncs0;
        out[OFF_CS + tid + 256] = ncs1;

        for (int d = 0; d < EMB_D; d++) {
            int i0 = d * N_EMB + tid;
            int i1 = i0 + 256;
            float s0 = 0.0f, s1 = 0.0f;
            #pragma unroll
            for (int r = 0; r < NREP; r++) {
                s0 += g_esumR[r][i0];
                s1 += g_esumR[r][i1];
            }
            float e0 = __fadd_rn(__fmul_rn(DEC, ea_in[i0]), __fmul_rn(OMD, s0));
            float e1 = __fadd_rn(__fmul_rn(DEC, ea_in[i1]), __fmul_rn(OMD, s1));
            out[OFF_EA + i0] = e0;
            out[OFF_EA + i1] = e1;
            out[OFF_W  + i0] = __fdiv_rn(e0, csn0);
            out[OFF_W  + i1] = __fdiv_rn(e1, csn1);
        }
    }
}

// ---------------------------------------------------------------------------
extern "C" void kernel_launch(void* const* d_in, const int* in_sizes, int n_in,
                              void* d_out, int out_size) {
    const float* x  = (const float*)d_in[0];
    const float* w  = (const float*)d_in[1];
    const float* cs = (const float*)d_in[2];
    const float* ea = (const float*)d_in[3];
    float* out = (float*)d_out;

    cudaFuncSetAttribute(assign_kernel,
                         cudaFuncAttributeMaxDynamicSharedMemorySize, SMEM_BYTES);

    prep_kernel<<<128, 256>>>(w);
    assign_kernel<<<GRID_A, TPB, SMEM_BYTES>>>(x, cs, ea, out);
}